// round 12
// baseline (speedup 1.0000x reference)
#include <cuda_runtime.h>
#include <cuda_fp16.h>
#include <cstdint>
#include <math.h>
#include <mma.h>

using namespace nvcuda;

#define SEQ    1024
#define NBATCH 2
#define BSTOT  2048      // B*S
#define NH     64
#define HD     32
#define DS     64
#define KPROJ  4432
#define DI     2048
#define DM     1024
#define EPSV   1e-5f

#define CHUNK  64
#define NC     16        // SEQ / CHUNK

// offsets inside one proj row of length KPROJ
#define OFF_Z   0
#define OFF_X   2048
#define OFF_B   4096
#define OFF_C   4160
#define OFF_DT  4224
#define OFF_A   4288
#define OFF_TR  4352
#define OFF_ANG 4416

// scratch layout (float units)
#define PROJ_OFF 0ull
#define AARR_OFF 9076736ull      // + BSTOT*KPROJ
#define GB_OFF   9207808ull      // + BSTOT*NH
#define CM_OFF   17596416ull     // + BSTOT*NH*DS
#define Y_OFF    25985024ull     // + BSTOT*NH*DS
#define HST_OFF  30179328ull     // + BSTOT*DI
#define PBUF_OFF 34373632ull     // + NBATCH*NH*NC*HD*DS
#define UH_OFF   34504704ull     // + BSTOT*NH            : half copy of u
#define WIH_OFF  35553280ull     // + BSTOT*DM/2          : half copy of W_in
#define WOH_OFF  37822464ull     // + KPROJ*DM/2          : half copy of W_out
#define YH_OFF   38871040ull     // + DM*DI/2             : half copy of Y
#define SCRATCH_TOTAL 40968192ull

__device__ __align__(16) float g_scratch[SCRATCH_TOTAL];

__device__ __forceinline__ float softplusf(float x) {
    return x > 20.f ? x : log1pf(expf(x));
}
__device__ __forceinline__ float sigmoidf_(float x) {
    return 1.f / (1.f + expf(-x));
}

__device__ __forceinline__ void cp_async16h(__half* smem_dst, const __half* gsrc, bool pred) {
    unsigned int saddr = (unsigned int)__cvta_generic_to_shared(smem_dst);
    int sz = pred ? 16 : 0;
    asm volatile("cp.async.cg.shared.global [%0], [%1], 16, %2;\n"
                 :: "r"(saddr), "l"(gsrc), "r"(sz));
}
#define CP_COMMIT() asm volatile("cp.async.commit_group;\n" ::: "memory")
#define CP_WAIT(n)  asm volatile("cp.async.wait_group %0;\n" :: "n"(n) : "memory")

// ---------------------------------------------------------------------------
// fp32 -> fp16 (RN), grid-stride, 8 elems/thread. n % 8 == 0.
// ---------------------------------------------------------------------------
__global__ __launch_bounds__(256) void round_half_kernel(
    const float* __restrict__ in, __half* __restrict__ out, int n)
{
    int i = (blockIdx.x * blockDim.x + threadIdx.x) * 8;
    int stride = gridDim.x * blockDim.x * 8;
    for (; i < n; i += stride) {
        float4 v0 = *reinterpret_cast<const float4*>(in + i);
        float4 v1 = *reinterpret_cast<const float4*>(in + i + 4);
        __half2 h0 = __floats2half2_rn(v0.x, v0.y);
        __half2 h1 = __floats2half2_rn(v0.z, v0.w);
        __half2 h2 = __floats2half2_rn(v1.x, v1.y);
        __half2 h3 = __floats2half2_rn(v1.z, v1.w);
        uint4 pack;
        pack.x = *reinterpret_cast<unsigned int*>(&h0);
        pack.y = *reinterpret_cast<unsigned int*>(&h1);
        pack.z = *reinterpret_cast<unsigned int*>(&h2);
        pack.w = *reinterpret_cast<unsigned int*>(&h3);
        *reinterpret_cast<uint4*>(out + i) = pack;
    }
}

// ---------------------------------------------------------------------------
// FP16 tensor-core NT GEMM (fp32 accumulate), cp.async 2-stage double buffer
// (the measured-best R10 structure), templated on BN.
//   BN=128: 8 warps 2x4, warp tile 64x32 (4x2 frags)  -> GEMM1
//   BN=64 : 8 warps 2x4, warp tile 64x16 (4x1 frags)  -> GEMM2 (2x blocks)
// Static smem: 2 stages * (128 + BN) * BKH halves.
// M%128==0, K%32==0, N%16==0.
// ---------------------------------------------------------------------------
#define BKH 40   // padded row stride in halves (80B): conflict-free ldmatrix

template <int BN>
__global__ __launch_bounds__(256, 2) void hgemm_nt(
    int M, int N, int K,
    const __half* __restrict__ A,
    const __half* __restrict__ B,
    float* __restrict__ C)
{
    constexpr int JF = BN / 64;        // acc columns per warp (2 or 1)
    constexpr int BITER = BN / 64;     // B-loader iterations

    __shared__ __half As[2][128 * BKH];
    __shared__ __half Bs[2][BN * BKH];

    const int tid = threadIdx.x;
    const int wid = tid >> 5;
    const int m0 = blockIdx.y * 128;
    const int n0 = blockIdx.x * BN;
    const int wm = (wid & 1) * 64;
    const int wn = (wid >> 1) * (16 * JF);

    const int lrow = tid >> 2;         // 0..63
    const int lch  = (tid & 3) * 8;    // half offset 0,8,16,24

    wmma::fragment<wmma::accumulator, 16, 16, 16, float> acc[4][JF];
#pragma unroll
    for (int i = 0; i < 4; ++i)
#pragma unroll
        for (int j = 0; j < JF; ++j)
            wmma::fill_fragment(acc[i][j], 0.f);

    auto load_stage = [&](int s, int kt) {
#pragma unroll
        for (int i = 0; i < 2; ++i) {
            int row = i * 64 + lrow;
            cp_async16h(&As[s][row * BKH + lch],
                        A + (size_t)(m0 + row) * K + kt + lch, true);
        }
#pragma unroll
        for (int i = 0; i < BITER; ++i) {
            int row = i * 64 + lrow;
            bool bp = (n0 + row) < N;
            cp_async16h(&Bs[s][row * BKH + lch],
                        B + (size_t)(n0 + row) * K + bp * ((size_t)kt + lch), bp);
        }
        CP_COMMIT();
    };

    const int nt = K >> 5;
    load_stage(0, 0);

    for (int it = 0; it < nt; ++it) {
        const int s = it & 1;
        if (it + 1 < nt) {
            load_stage(s ^ 1, (it + 1) << 5);
            CP_WAIT(1);
        } else {
            CP_WAIT(0);
        }
        __syncthreads();

        const __half* Asm = As[s];
        const __half* Bsm = Bs[s];
#pragma unroll
        for (int k16 = 0; k16 < 32; k16 += 16) {
            wmma::fragment<wmma::matrix_b, 16, 16, 16, __half, wmma::col_major> bf[JF];
#pragma unroll
            for (int j = 0; j < JF; ++j)
                wmma::load_matrix_sync(bf[j], Bsm + (wn + j * 16) * BKH + k16, BKH);
#pragma unroll
            for (int i = 0; i < 4; ++i) {
                wmma::fragment<wmma::matrix_a, 16, 16, 16, __half, wmma::row_major> af;
                wmma::load_matrix_sync(af, Asm + (wm + i * 16) * BKH + k16, BKH);
#pragma unroll
                for (int j = 0; j < JF; ++j)
                    wmma::mma_sync(acc[i][j], af, bf[j], acc[i][j]);
            }
        }
        __syncthreads();
    }

#pragma unroll
    for (int i = 0; i < 4; ++i) {
#pragma unroll
        for (int j = 0; j < JF; ++j) {
            int cc = n0 + wn + j * 16;
            if (cc < N)
                wmma::store_matrix_sync(
                    C + (size_t)(m0 + wm + i * 16) * N + cc,
                    acc[i][j], N, wmma::mem_row_major);
        }
    }
}

// ---------------------------------------------------------------------------
// Prep: per (b,s) row of proj, compute a[b,s,h], gdtB[b,s,h,n], Cm[b,s,h,n]
// ---------------------------------------------------------------------------
__global__ __launch_bounds__(128) void prep_kernel(
    const float* __restrict__ dt_bias,
    const float* __restrict__ B_bias,
    const float* __restrict__ C_bias,
    const float* __restrict__ Bn_w,
    const float* __restrict__ Cn_w)
{
    const int bs = blockIdx.x;
    const int tid = threadIdx.x;
    const float* row = g_scratch + PROJ_OFF + (size_t)bs * KPROJ;

    __shared__ float normB[64], normC[64];
    __shared__ float cs[16], sn[16];
    __shared__ float gdt_s[64];
    __shared__ float red[4];

    float v = (tid < 64) ? row[OFF_B + tid] : row[OFF_C + (tid - 64)];
    float sq = v * v;
#pragma unroll
    for (int o = 16; o > 0; o >>= 1) sq += __shfl_xor_sync(0xffffffffu, sq, o);
    if ((tid & 31) == 0) red[tid >> 5] = sq;
    __syncthreads();
    float rB = rsqrtf((red[0] + red[1]) * (1.f / 64.f) + EPSV);
    float rC = rsqrtf((red[2] + red[3]) * (1.f / 64.f) + EPSV);
    if (tid < 64) normB[tid] = v * rB * Bn_w[tid];
    else          normC[tid - 64] = v * rC * Cn_w[tid - 64];

    if (tid < 64) {
        int h = tid;
        float dt = softplusf(row[OFF_DT + h] + dt_bias[h]);
        float A  = fminf(-softplusf(row[OFF_A + h]), -1e-4f);
        float trap = sigmoidf_(row[OFF_TR + h]);
        float g = 1.f - 0.5f * trap;
        float a = g * expf(A * dt) + 0.5f * trap;
        g_scratch[AARR_OFF + (size_t)bs * NH + h] = a;
        gdt_s[h] = g * dt;
    }
    if (tid < 16) {
        float ang = row[OFF_ANG + tid];
        cs[tid] = cosf(ang);
        sn[tid] = sinf(ang);
    }
    __syncthreads();

    float* gb_out = g_scratch + GB_OFF + (size_t)bs * (NH * DS);
    float* cm_out = g_scratch + CM_OFF + (size_t)bs * (NH * DS);
#pragma unroll
    for (int it = 0; it < 32; ++it) {
        int i = it * 128 + tid;
        int h = i >> 6;
        int n = i & 63;
        float vB = normB[n] + B_bias[i];
        float vC = normC[n] + C_bias[i];
        float oB, oC;
        if (n < 16) {
            float b2 = normB[n + 16] + B_bias[h * 64 + n + 16];
            float c2 = normC[n + 16] + C_bias[h * 64 + n + 16];
            oB = vB * cs[n] - b2 * sn[n];
            oC = vC * cs[n] - c2 * sn[n];
        } else if (n < 32) {
            int j = n - 16;
            float b1 = normB[j] + B_bias[h * 64 + j];
            float c1 = normC[j] + C_bias[h * 64 + j];
            oB = b1 * sn[j] + vB * cs[j];
            oC = c1 * sn[j] + vC * cs[j];
        } else {
            oB = vB;
            oC = vC;
        }
        gb_out[i] = gdt_s[h] * oB;
        cm_out[i] = oC;
    }
}

// ---------------------------------------------------------------------------
// Pass 1: local scan within each chunk (h0 = 0).
// ---------------------------------------------------------------------------
__global__ __launch_bounds__(256) void scan_chunk_kernel(const float* __restrict__ Dv)
{
    const int bx = blockIdx.x;
    const int c = bx & (NC - 1);
    const int h = (bx >> 4) & (NH - 1);
    const int b = bx >> 10;
    const int tid = threadIdx.x;
    const int p = tid >> 3;
    const int ng = tid & 7;
    const int n0 = ng * 8;

    const float Dh = Dv[h];

    float hs0 = 0.f, hs1 = 0.f, hs2 = 0.f, hs3 = 0.f;
    float hs4 = 0.f, hs5 = 0.f, hs6 = 0.f, hs7 = 0.f;
    float P = 1.f;

    const float* proj = g_scratch + PROJ_OFF;
    const float* aarr = g_scratch + AARR_OFF;
    const float* gbb  = g_scratch + GB_OFF;
    const float* cmb  = g_scratch + CM_OFF;
    float* Yb = g_scratch + Y_OFF;
    float* Pb = g_scratch + PBUF_OFF;

    const int t0 = c * CHUNK;

#pragma unroll 2
    for (int t = 0; t < CHUNK; ++t) {
        const size_t bs = (size_t)b * SEQ + t0 + t;
        const size_t idx = bs * NH + h;

        float a = aarr[idx];
        const float4* g4 = reinterpret_cast<const float4*>(gbb + idx * DS + n0);
        const float4* c4 = reinterpret_cast<const float4*>(cmb + idx * DS + n0);
        float4 g0 = g4[0], g1 = g4[1];
        float4 c0 = c4[0], c1 = c4[1];
        float x = proj[bs * KPROJ + OFF_X + h * HD + p];

        P *= a;

        hs0 = fmaf(a, hs0, x * g0.x);
        hs1 = fmaf(a, hs1, x * g0.y);
        hs2 = fmaf(a, hs2, x * g0.z);
        hs3 = fmaf(a, hs3, x * g0.w);
        hs4 = fmaf(a, hs4, x * g1.x);
        hs5 = fmaf(a, hs5, x * g1.y);
        hs6 = fmaf(a, hs6, x * g1.z);
        hs7 = fmaf(a, hs7, x * g1.w);

        float pa = fmaf(hs1, c0.y, hs0 * c0.x);
        float pb2 = fmaf(hs3, c0.w, hs2 * c0.z);
        float pc = fmaf(hs5, c1.y, hs4 * c1.x);
        float pd = fmaf(hs7, c1.w, hs6 * c1.z);
        float part = (pa + pb2) + (pc + pd);

        part += __shfl_down_sync(0xffffffffu, part, 4, 8);
        part += __shfl_down_sync(0xffffffffu, part, 2, 8);
        part += __shfl_down_sync(0xffffffffu, part, 1, 8);

        if (ng == 0) {
            Yb[bs * DI + h * HD + p] = part + Dh * x;
        }
        if (tid == 0) {
            Pb[idx] = P;
        }
    }

    float* hst = g_scratch + HST_OFF +
                 (((size_t)(b * NH + h) * NC + c) * (HD * DS)) + p * DS + n0;
    reinterpret_cast<float4*>(hst)[0] = make_float4(hs0, hs1, hs2, hs3);
    reinterpret_cast<float4*>(hst)[1] = make_float4(hs4, hs5, hs6, hs7);
}

// ---------------------------------------------------------------------------
// Pass 2: sequential combine of chunk states into prefix end-states.
// ---------------------------------------------------------------------------
__global__ __launch_bounds__(256) void combine_kernel()
{
    const int bh = blockIdx.x;
    const int b = bh >> 6;
    const int h = bh & 63;
    const int tid = threadIdx.x;
    const int e = tid * 8;

    float* base = g_scratch + HST_OFF + (size_t)bh * NC * (HD * DS);
    const float* Pb = g_scratch + PBUF_OFF;

    float4 H0 = reinterpret_cast<float4*>(base + e)[0];
    float4 H1 = reinterpret_cast<float4*>(base + e)[1];

    for (int c = 1; c < NC; ++c) {
        float Atot = Pb[((size_t)b * SEQ + c * CHUNK + CHUNK - 1) * NH + h];
        float* ptr = base + (size_t)c * (HD * DS) + e;
        float4 L0 = reinterpret_cast<float4*>(ptr)[0];
        float4 L1 = reinterpret_cast<float4*>(ptr)[1];
        H0.x = fmaf(Atot, H0.x, L0.x); H0.y = fmaf(Atot, H0.y, L0.y);
        H0.z = fmaf(Atot, H0.z, L0.z); H0.w = fmaf(Atot, H0.w, L0.w);
        H1.x = fmaf(Atot, H1.x, L1.x); H1.y = fmaf(Atot, H1.y, L1.y);
        H1.z = fmaf(Atot, H1.z, L1.z); H1.w = fmaf(Atot, H1.w, L1.w);
        reinterpret_cast<float4*>(ptr)[0] = H0;
        reinterpret_cast<float4*>(ptr)[1] = H1;
    }
}

// ---------------------------------------------------------------------------
// Pass 3: y += P_t * (C_t . H_prev), then * silu(z); write fp16 Y for GEMM2.
// ---------------------------------------------------------------------------
__global__ __launch_bounds__(256) void fixup_kernel()
{
    const int bx = blockIdx.x;
    const int c = bx & (NC - 1);
    const int h = (bx >> 4) & (NH - 1);
    const int b = bx >> 10;
    const int tid = threadIdx.x;
    const int p = tid >> 3;
    const int ng = tid & 7;
    const int n0 = ng * 8;

    const float* proj = g_scratch + PROJ_OFF;
    const float* cmb  = g_scratch + CM_OFF;
    const float* Pb   = g_scratch + PBUF_OFF;
    const float* Yb   = g_scratch + Y_OFF;
    __half* Yh = reinterpret_cast<__half*>(g_scratch + YH_OFF);

    float4 hp0 = make_float4(0.f, 0.f, 0.f, 0.f);
    float4 hp1 = make_float4(0.f, 0.f, 0.f, 0.f);
    if (c > 0) {
        const float* hst = g_scratch + HST_OFF +
            (((size_t)(b * NH + h) * NC + (c - 1)) * (HD * DS)) + p * DS + n0;
        hp0 = reinterpret_cast<const float4*>(hst)[0];
        hp1 = reinterpret_cast<const float4*>(hst)[1];
    }

    const int t0 = c * CHUNK;

#pragma unroll 4
    for (int t = 0; t < CHUNK; ++t) {
        const size_t bs = (size_t)b * SEQ + t0 + t;
        const size_t idx = bs * NH + h;

        const float4* c4 = reinterpret_cast<const float4*>(cmb + idx * DS + n0);
        float4 c0 = c4[0], c1 = c4[1];

        float pa = fmaf(hp0.y, c0.y, hp0.x * c0.x);
        float pb2 = fmaf(hp0.w, c0.w, hp0.z * c0.z);
        float pc = fmaf(hp1.y, c1.y, hp1.x * c1.x);
        float pd = fmaf(hp1.w, c1.w, hp1.z * c1.z);
        float part = (pa + pb2) + (pc + pd);

        part += __shfl_down_sync(0xffffffffu, part, 4, 8);
        part += __shfl_down_sync(0xffffffffu, part, 2, 8);
        part += __shfl_down_sync(0xffffffffu, part, 1, 8);

        if (ng == 0) {
            float y = Yb[bs * DI + h * HD + p];
            if (c > 0) {
                y = fmaf(Pb[idx], part, y);
            }
            float z = proj[bs * KPROJ + OFF_Z + h * HD + p];
            float silu = z * sigmoidf_(z);
            Yh[bs * DI + h * HD + p] = __float2half_rn(y * silu);
        }
    }
}

// ---------------------------------------------------------------------------
extern "C" void kernel_launch(void* const* d_in, const int* in_sizes, int n_in,
                              void* d_out, int out_size)
{
    const float* u       = (const float*)d_in[0];
    const float* W_in    = (const float*)d_in[1];
    const float* dt_bias = (const float*)d_in[2];
    const float* B_bias  = (const float*)d_in[3];
    const float* C_bias  = (const float*)d_in[4];
    const float* Bn_w    = (const float*)d_in[5];
    const float* Cn_w    = (const float*)d_in[6];
    const float* Dv      = (const float*)d_in[7];
    const float* W_out   = (const float*)d_in[8];
    float* out = (float*)d_out;

    float* scratch = nullptr;
    cudaGetSymbolAddress((void**)&scratch, g_scratch);

    float* proj = scratch + PROJ_OFF;
    __half* u_h  = reinterpret_cast<__half*>(scratch + UH_OFF);
    __half* Wi_h = reinterpret_cast<__half*>(scratch + WIH_OFF);
    __half* Wo_h = reinterpret_cast<__half*>(scratch + WOH_OFF);
    __half* Yh   = reinterpret_cast<__half*>(scratch + YH_OFF);

    // Convert GEMM operands to fp16
    round_half_kernel<<<296, 256>>>(u,     u_h,  BSTOT * DM);
    round_half_kernel<<<296, 256>>>(W_in,  Wi_h, KPROJ * DM);
    round_half_kernel<<<296, 256>>>(W_out, Wo_h, DM * DI);

    // GEMM1: proj[BSTOT, KPROJ] = u @ W_in^T  (fp16 in, fp32 accum)
    {
        dim3 grid((KPROJ + 127) / 128, BSTOT / 128);
        hgemm_nt<128><<<grid, 256>>>(BSTOT, KPROJ, DM, u_h, Wi_h, proj);
    }

    prep_kernel<<<BSTOT, 128>>>(dt_bias, B_bias, C_bias, Bn_w, Cn_w);

    // chunked scan
    scan_chunk_kernel<<<NBATCH * NH * NC, 256>>>(Dv);
    combine_kernel<<<NBATCH * NH, 256>>>();
    fixup_kernel<<<NBATCH * NH * NC, 256>>>();

    // GEMM2: out[BSTOT, DM] = Y @ W_out^T  (fp16 in, fp32 accum, BN=64)
    {
        dim3 grid(DM / 64, BSTOT / 128);
        hgemm_nt<64><<<grid, 256>>>(BSTOT, DM, DI, Yh, Wo_h, out);
    }
}

// round 13
// speedup vs baseline: 1.0372x; 1.0372x over previous
#include <cuda_runtime.h>
#include <cuda_fp16.h>
#include <cstdint>
#include <math.h>
#include <mma.h>

using namespace nvcuda;

#define SEQ    1024
#define NBATCH 2
#define BSTOT  2048      // B*S
#define NH     64
#define HD     32
#define DS     64
#define KPROJ  4432
#define DI     2048
#define DM     1024
#define EPSV   1e-5f

#define CHUNK  64
#define NC     16        // SEQ / CHUNK

// offsets inside one proj row of length KPROJ
#define OFF_Z   0
#define OFF_X   2048
#define OFF_B   4096
#define OFF_C   4160
#define OFF_DT  4224
#define OFF_A   4288
#define OFF_TR  4352
#define OFF_ANG 4416

// scratch layout (float units)
#define PROJ_OFF 0ull
#define AARR_OFF 9076736ull      // + BSTOT*KPROJ
#define GB_OFF   9207808ull      // + BSTOT*NH
#define CM_OFF   17596416ull     // + BSTOT*NH*DS
#define Y_OFF    25985024ull     // + BSTOT*NH*DS
#define HST_OFF  30179328ull     // + BSTOT*DI
#define PBUF_OFF 34373632ull     // + NBATCH*NH*NC*HD*DS
#define UH_OFF   34504704ull     // + BSTOT*NH            : half copy of u
#define WIH_OFF  35553280ull     // + BSTOT*DM/2          : half copy of W_in
#define WOH_OFF  37822464ull     // + KPROJ*DM/2          : half copy of W_out
#define YH_OFF   38871040ull     // + DM*DI/2             : half copy of Y
#define SCRATCH_TOTAL 40968192ull

// converter segment sizes (elements)
#define N_U  (BSTOT * DM)    // 2097152
#define N_WI (KPROJ * DM)    // 4538368
#define N_WO (DM * DI)       // 2097152

__device__ __align__(16) float g_scratch[SCRATCH_TOTAL];

__device__ __forceinline__ float softplusf(float x) {
    return x > 20.f ? x : log1pf(expf(x));
}
__device__ __forceinline__ float sigmoidf_(float x) {
    return 1.f / (1.f + expf(-x));
}

__device__ __forceinline__ void cp_async16h(__half* smem_dst, const __half* gsrc, bool pred) {
    unsigned int saddr = (unsigned int)__cvta_generic_to_shared(smem_dst);
    int sz = pred ? 16 : 0;
    asm volatile("cp.async.cg.shared.global [%0], [%1], 16, %2;\n"
                 :: "r"(saddr), "l"(gsrc), "r"(sz));
}
#define CP_COMMIT() asm volatile("cp.async.commit_group;\n" ::: "memory")
#define CP_WAIT(n)  asm volatile("cp.async.wait_group %0;\n" :: "n"(n) : "memory")

// ---------------------------------------------------------------------------
// Fused fp32 -> fp16 converter for u, W_in, W_out in ONE launch.
// Grid-stride over the concatenated length; segment lookup per index.
// ---------------------------------------------------------------------------
__global__ __launch_bounds__(256) void convert_all_kernel(
    const float* __restrict__ u,
    const float* __restrict__ W_in,
    const float* __restrict__ W_out)
{
    __half* u_h  = reinterpret_cast<__half*>(g_scratch + UH_OFF);
    __half* Wi_h = reinterpret_cast<__half*>(g_scratch + WIH_OFF);
    __half* Wo_h = reinterpret_cast<__half*>(g_scratch + WOH_OFF);

    const int total = (N_U + N_WI + N_WO) / 8;   // 8 elems per thread-step
    int idx = blockIdx.x * blockDim.x + threadIdx.x;
    int stride = gridDim.x * blockDim.x;

    for (; idx < total; idx += stride) {
        int i = idx * 8;
        const float* src;
        __half* dst;
        if (i < N_U)                { src = u + i;                dst = u_h + i; }
        else if (i < N_U + N_WI)    { src = W_in + (i - N_U);     dst = Wi_h + (i - N_U); }
        else                        { src = W_out + (i - N_U - N_WI); dst = Wo_h + (i - N_U - N_WI); }

        float4 v0 = *reinterpret_cast<const float4*>(src);
        float4 v1 = *reinterpret_cast<const float4*>(src + 4);
        __half2 h0 = __floats2half2_rn(v0.x, v0.y);
        __half2 h1 = __floats2half2_rn(v0.z, v0.w);
        __half2 h2 = __floats2half2_rn(v1.x, v1.y);
        __half2 h3 = __floats2half2_rn(v1.z, v1.w);
        uint4 pack;
        pack.x = *reinterpret_cast<unsigned int*>(&h0);
        pack.y = *reinterpret_cast<unsigned int*>(&h1);
        pack.z = *reinterpret_cast<unsigned int*>(&h2);
        pack.w = *reinterpret_cast<unsigned int*>(&h3);
        *reinterpret_cast<uint4*>(dst) = pack;
    }
}

// ---------------------------------------------------------------------------
// FP16 tensor-core NT GEMM (fp32 accumulate), cp.async 2-stage double buffer.
// EXACT R10 structure (measured 68.7us GEMM1 / 489us total).
// C[M,N] = A[M,K]*B[N,K]^T. Block 128x128, BK=32, 8 warps (2x4),
// warp tile 64x32 = wmma m16n16k16, 2 k-steps per BK iter.
// Static smem: 2 stages * 2 tiles * 128*BKH halves = 40960 B.
// M%128==0, K%32==0, N%16==0.
// ---------------------------------------------------------------------------
#define BKH 40   // padded row stride in halves (80B): conflict-free ldmatrix

__global__ __launch_bounds__(256, 2) void hgemm_nt(
    int M, int N, int K,
    const __half* __restrict__ A,
    const __half* __restrict__ B,
    float* __restrict__ C)
{
    __shared__ __half As[2][128 * BKH];
    __shared__ __half Bs[2][128 * BKH];

    const int tid = threadIdx.x;
    const int wid = tid >> 5;
    const int m0 = blockIdx.y * 128;
    const int n0 = blockIdx.x * 128;
    const int wm = (wid & 1) * 64;
    const int wn = (wid >> 1) * 32;

    const int lrow = tid >> 2;         // 0..63
    const int lch  = (tid & 3) * 8;    // half offset 0,8,16,24

    wmma::fragment<wmma::accumulator, 16, 16, 16, float> acc[4][2];
#pragma unroll
    for (int i = 0; i < 4; ++i)
#pragma unroll
        for (int j = 0; j < 2; ++j)
            wmma::fill_fragment(acc[i][j], 0.f);

    auto load_stage = [&](int s, int kt) {
#pragma unroll
        for (int i = 0; i < 2; ++i) {
            int row = i * 64 + lrow;
            cp_async16h(&As[s][row * BKH + lch],
                        A + (size_t)(m0 + row) * K + kt + lch, true);
            bool bp = (n0 + row) < N;
            cp_async16h(&Bs[s][row * BKH + lch],
                        B + (size_t)(n0 + row) * K + bp * ((size_t)kt + lch), bp);
        }
        CP_COMMIT();
    };

    const int nt = K >> 5;
    load_stage(0, 0);

    for (int it = 0; it < nt; ++it) {
        const int s = it & 1;
        if (it + 1 < nt) {
            load_stage(s ^ 1, (it + 1) << 5);
            CP_WAIT(1);
        } else {
            CP_WAIT(0);
        }
        __syncthreads();

        const __half* Asm = As[s];
        const __half* Bsm = Bs[s];
#pragma unroll
        for (int k16 = 0; k16 < 32; k16 += 16) {
            wmma::fragment<wmma::matrix_b, 16, 16, 16, __half, wmma::col_major> bf[2];
#pragma unroll
            for (int j = 0; j < 2; ++j)
                wmma::load_matrix_sync(bf[j], Bsm + (wn + j * 16) * BKH + k16, BKH);
#pragma unroll
            for (int i = 0; i < 4; ++i) {
                wmma::fragment<wmma::matrix_a, 16, 16, 16, __half, wmma::row_major> af;
                wmma::load_matrix_sync(af, Asm + (wm + i * 16) * BKH + k16, BKH);
                wmma::mma_sync(acc[i][0], af, bf[0], acc[i][0]);
                wmma::mma_sync(acc[i][1], af, bf[1], acc[i][1]);
            }
        }
        __syncthreads();
    }

#pragma unroll
    for (int i = 0; i < 4; ++i) {
#pragma unroll
        for (int j = 0; j < 2; ++j) {
            int cc = n0 + wn + j * 16;
            if (cc < N)
                wmma::store_matrix_sync(
                    C + (size_t)(m0 + wm + i * 16) * N + cc,
                    acc[i][j], N, wmma::mem_row_major);
        }
    }
}

// ---------------------------------------------------------------------------
// Prep: per (b,s) row of proj, compute a[b,s,h], gdtB[b,s,h,n], Cm[b,s,h,n]
// ---------------------------------------------------------------------------
__global__ __launch_bounds__(128) void prep_kernel(
    const float* __restrict__ dt_bias,
    const float* __restrict__ B_bias,
    const float* __restrict__ C_bias,
    const float* __restrict__ Bn_w,
    const float* __restrict__ Cn_w)
{
    const int bs = blockIdx.x;
    const int tid = threadIdx.x;
    const float* row = g_scratch + PROJ_OFF + (size_t)bs * KPROJ;

    __shared__ float normB[64], normC[64];
    __shared__ float cs[16], sn[16];
    __shared__ float gdt_s[64];
    __shared__ float red[4];

    float v = (tid < 64) ? row[OFF_B + tid] : row[OFF_C + (tid - 64)];
    float sq = v * v;
#pragma unroll
    for (int o = 16; o > 0; o >>= 1) sq += __shfl_xor_sync(0xffffffffu, sq, o);
    if ((tid & 31) == 0) red[tid >> 5] = sq;
    __syncthreads();
    float rB = rsqrtf((red[0] + red[1]) * (1.f / 64.f) + EPSV);
    float rC = rsqrtf((red[2] + red[3]) * (1.f / 64.f) + EPSV);
    if (tid < 64) normB[tid] = v * rB * Bn_w[tid];
    else          normC[tid - 64] = v * rC * Cn_w[tid - 64];

    if (tid < 64) {
        int h = tid;
        float dt = softplusf(row[OFF_DT + h] + dt_bias[h]);
        float A  = fminf(-softplusf(row[OFF_A + h]), -1e-4f);
        float trap = sigmoidf_(row[OFF_TR + h]);
        float g = 1.f - 0.5f * trap;
        float a = g * expf(A * dt) + 0.5f * trap;
        g_scratch[AARR_OFF + (size_t)bs * NH + h] = a;
        gdt_s[h] = g * dt;
    }
    if (tid < 16) {
        float ang = row[OFF_ANG + tid];
        cs[tid] = cosf(ang);
        sn[tid] = sinf(ang);
    }
    __syncthreads();

    float* gb_out = g_scratch + GB_OFF + (size_t)bs * (NH * DS);
    float* cm_out = g_scratch + CM_OFF + (size_t)bs * (NH * DS);
#pragma unroll
    for (int it = 0; it < 32; ++it) {
        int i = it * 128 + tid;
        int h = i >> 6;
        int n = i & 63;
        float vB = normB[n] + B_bias[i];
        float vC = normC[n] + C_bias[i];
        float oB, oC;
        if (n < 16) {
            float b2 = normB[n + 16] + B_bias[h * 64 + n + 16];
            float c2 = normC[n + 16] + C_bias[h * 64 + n + 16];
            oB = vB * cs[n] - b2 * sn[n];
            oC = vC * cs[n] - c2 * sn[n];
        } else if (n < 32) {
            int j = n - 16;
            float b1 = normB[j] + B_bias[h * 64 + j];
            float c1 = normC[j] + C_bias[h * 64 + j];
            oB = b1 * sn[j] + vB * cs[j];
            oC = c1 * sn[j] + vC * cs[j];
        } else {
            oB = vB;
            oC = vC;
        }
        gb_out[i] = gdt_s[h] * oB;
        cm_out[i] = oC;
    }
}

// ---------------------------------------------------------------------------
// Pass 1: local scan within each chunk (h0 = 0).
// ---------------------------------------------------------------------------
__global__ __launch_bounds__(256) void scan_chunk_kernel(const float* __restrict__ Dv)
{
    const int bx = blockIdx.x;
    const int c = bx & (NC - 1);
    const int h = (bx >> 4) & (NH - 1);
    const int b = bx >> 10;
    const int tid = threadIdx.x;
    const int p = tid >> 3;
    const int ng = tid & 7;
    const int n0 = ng * 8;

    const float Dh = Dv[h];

    float hs0 = 0.f, hs1 = 0.f, hs2 = 0.f, hs3 = 0.f;
    float hs4 = 0.f, hs5 = 0.f, hs6 = 0.f, hs7 = 0.f;
    float P = 1.f;

    const float* proj = g_scratch + PROJ_OFF;
    const float* aarr = g_scratch + AARR_OFF;
    const float* gbb  = g_scratch + GB_OFF;
    const float* cmb  = g_scratch + CM_OFF;
    float* Yb = g_scratch + Y_OFF;
    float* Pb = g_scratch + PBUF_OFF;

    const int t0 = c * CHUNK;

#pragma unroll 2
    for (int t = 0; t < CHUNK; ++t) {
        const size_t bs = (size_t)b * SEQ + t0 + t;
        const size_t idx = bs * NH + h;

        float a = aarr[idx];
        const float4* g4 = reinterpret_cast<const float4*>(gbb + idx * DS + n0);
        const float4* c4 = reinterpret_cast<const float4*>(cmb + idx * DS + n0);
        float4 g0 = g4[0], g1 = g4[1];
        float4 c0 = c4[0], c1 = c4[1];
        float x = proj[bs * KPROJ + OFF_X + h * HD + p];

        P *= a;

        hs0 = fmaf(a, hs0, x * g0.x);
        hs1 = fmaf(a, hs1, x * g0.y);
        hs2 = fmaf(a, hs2, x * g0.z);
        hs3 = fmaf(a, hs3, x * g0.w);
        hs4 = fmaf(a, hs4, x * g1.x);
        hs5 = fmaf(a, hs5, x * g1.y);
        hs6 = fmaf(a, hs6, x * g1.z);
        hs7 = fmaf(a, hs7, x * g1.w);

        float pa = fmaf(hs1, c0.y, hs0 * c0.x);
        float pb2 = fmaf(hs3, c0.w, hs2 * c0.z);
        float pc = fmaf(hs5, c1.y, hs4 * c1.x);
        float pd = fmaf(hs7, c1.w, hs6 * c1.z);
        float part = (pa + pb2) + (pc + pd);

        part += __shfl_down_sync(0xffffffffu, part, 4, 8);
        part += __shfl_down_sync(0xffffffffu, part, 2, 8);
        part += __shfl_down_sync(0xffffffffu, part, 1, 8);

        if (ng == 0) {
            Yb[bs * DI + h * HD + p] = part + Dh * x;
        }
        if (tid == 0) {
            Pb[idx] = P;
        }
    }

    float* hst = g_scratch + HST_OFF +
                 (((size_t)(b * NH + h) * NC + c) * (HD * DS)) + p * DS + n0;
    reinterpret_cast<float4*>(hst)[0] = make_float4(hs0, hs1, hs2, hs3);
    reinterpret_cast<float4*>(hst)[1] = make_float4(hs4, hs5, hs6, hs7);
}

// ---------------------------------------------------------------------------
// Pass 2: sequential combine of chunk states into prefix end-states.
// ---------------------------------------------------------------------------
__global__ __launch_bounds__(256) void combine_kernel()
{
    const int bh = blockIdx.x;
    const int b = bh >> 6;
    const int h = bh & 63;
    const int tid = threadIdx.x;
    const int e = tid * 8;

    float* base = g_scratch + HST_OFF + (size_t)bh * NC * (HD * DS);
    const float* Pb = g_scratch + PBUF_OFF;

    float4 H0 = reinterpret_cast<float4*>(base + e)[0];
    float4 H1 = reinterpret_cast<float4*>(base + e)[1];

    for (int c = 1; c < NC; ++c) {
        float Atot = Pb[((size_t)b * SEQ + c * CHUNK + CHUNK - 1) * NH + h];
        float* ptr = base + (size_t)c * (HD * DS) + e;
        float4 L0 = reinterpret_cast<float4*>(ptr)[0];
        float4 L1 = reinterpret_cast<float4*>(ptr)[1];
        H0.x = fmaf(Atot, H0.x, L0.x); H0.y = fmaf(Atot, H0.y, L0.y);
        H0.z = fmaf(Atot, H0.z, L0.z); H0.w = fmaf(Atot, H0.w, L0.w);
        H1.x = fmaf(Atot, H1.x, L1.x); H1.y = fmaf(Atot, H1.y, L1.y);
        H1.z = fmaf(Atot, H1.z, L1.z); H1.w = fmaf(Atot, H1.w, L1.w);
        reinterpret_cast<float4*>(ptr)[0] = H0;
        reinterpret_cast<float4*>(ptr)[1] = H1;
    }
}

// ---------------------------------------------------------------------------
// Pass 3: y += P_t * (C_t . H_prev), then * silu(z); write fp16 Y for GEMM2.
// ---------------------------------------------------------------------------
__global__ __launch_bounds__(256) void fixup_kernel()
{
    const int bx = blockIdx.x;
    const int c = bx & (NC - 1);
    const int h = (bx >> 4) & (NH - 1);
    const int b = bx >> 10;
    const int tid = threadIdx.x;
    const int p = tid >> 3;
    const int ng = tid & 7;
    const int n0 = ng * 8;

    const float* proj = g_scratch + PROJ_OFF;
    const float* cmb  = g_scratch + CM_OFF;
    const float* Pb   = g_scratch + PBUF_OFF;
    const float* Yb   = g_scratch + Y_OFF;
    __half* Yh = reinterpret_cast<__half*>(g_scratch + YH_OFF);

    float4 hp0 = make_float4(0.f, 0.f, 0.f, 0.f);
    float4 hp1 = make_float4(0.f, 0.f, 0.f, 0.f);
    if (c > 0) {
        const float* hst = g_scratch + HST_OFF +
            (((size_t)(b * NH + h) * NC + (c - 1)) * (HD * DS)) + p * DS + n0;
        hp0 = reinterpret_cast<const float4*>(hst)[0];
        hp1 = reinterpret_cast<const float4*>(hst)[1];
    }

    const int t0 = c * CHUNK;

#pragma unroll 4
    for (int t = 0; t < CHUNK; ++t) {
        const size_t bs = (size_t)b * SEQ + t0 + t;
        const size_t idx = bs * NH + h;

        const float4* c4 = reinterpret_cast<const float4*>(cmb + idx * DS + n0);
        float4 c0 = c4[0], c1 = c4[1];

        float pa = fmaf(hp0.y, c0.y, hp0.x * c0.x);
        float pb2 = fmaf(hp0.w, c0.w, hp0.z * c0.z);
        float pc = fmaf(hp1.y, c1.y, hp1.x * c1.x);
        float pd = fmaf(hp1.w, c1.w, hp1.z * c1.z);
        float part = (pa + pb2) + (pc + pd);

        part += __shfl_down_sync(0xffffffffu, part, 4, 8);
        part += __shfl_down_sync(0xffffffffu, part, 2, 8);
        part += __shfl_down_sync(0xffffffffu, part, 1, 8);

        if (ng == 0) {
            float y = Yb[bs * DI + h * HD + p];
            if (c > 0) {
                y = fmaf(Pb[idx], part, y);
            }
            float z = proj[bs * KPROJ + OFF_Z + h * HD + p];
            float silu = z * sigmoidf_(z);
            Yh[bs * DI + h * HD + p] = __float2half_rn(y * silu);
        }
    }
}

// ---------------------------------------------------------------------------
extern "C" void kernel_launch(void* const* d_in, const int* in_sizes, int n_in,
                              void* d_out, int out_size)
{
    const float* u       = (const float*)d_in[0];
    const float* W_in    = (const float*)d_in[1];
    const float* dt_bias = (const float*)d_in[2];
    const float* B_bias  = (const float*)d_in[3];
    const float* C_bias  = (const float*)d_in[4];
    const float* Bn_w    = (const float*)d_in[5];
    const float* Cn_w    = (const float*)d_in[6];
    const float* Dv      = (const float*)d_in[7];
    const float* W_out   = (const float*)d_in[8];
    float* out = (float*)d_out;

    float* scratch = nullptr;
    cudaGetSymbolAddress((void**)&scratch, g_scratch);

    float* proj = scratch + PROJ_OFF;
    __half* u_h  = reinterpret_cast<__half*>(scratch + UH_OFF);
    __half* Wi_h = reinterpret_cast<__half*>(scratch + WIH_OFF);
    __half* Wo_h = reinterpret_cast<__half*>(scratch + WOH_OFF);
    __half* Yh   = reinterpret_cast<__half*>(scratch + YH_OFF);

    // Convert all GEMM operands to fp16 in ONE launch
    convert_all_kernel<<<888, 256>>>(u, W_in, W_out);

    // GEMM1: proj[BSTOT, KPROJ] = u @ W_in^T  (fp16 in, fp32 accum)
    {
        dim3 grid((KPROJ + 127) / 128, BSTOT / 128);
        hgemm_nt<<<grid, 256>>>(BSTOT, KPROJ, DM, u_h, Wi_h, proj);
    }

    prep_kernel<<<BSTOT, 128>>>(dt_bias, B_bias, C_bias, Bn_w, Cn_w);

    // chunked scan
    scan_chunk_kernel<<<NBATCH * NH * NC, 256>>>(Dv);
    combine_kernel<<<NBATCH * NH, 256>>>();
    fixup_kernel<<<NBATCH * NH * NC, 256>>>();

    // GEMM2: out[BSTOT, DM] = Y @ W_out^T  (fp16 in, fp32 accum, BN=128)
    {
        dim3 grid(DM / 128, BSTOT / 128);
        hgemm_nt<<<grid, 256>>>(BSTOT, DM, DI, Yh, Wo_h, out);
    }
}